// round 11
// baseline (speedup 1.0000x reference)
#include <cuda_runtime.h>

#define BB   512   // batch
#define TT   512   // seq len
#define FF   32    // features
#define HH   128   // hidden
#define G4   512   // 4*H
#define LL   5     // labels

#define SROWS 416  // gate rows resident in shared (rest streamed from L2)
#define TPB   256

typedef unsigned long long u64;

// ---------------- f32x2 helpers (FFMA2 only reachable via PTX) ----------------
__device__ __forceinline__ u64 fma2(u64 a, u64 b, u64 c) {
    u64 d;
    asm("fma.rn.f32x2 %0, %1, %2, %3;" : "=l"(d) : "l"(a), "l"(b), "l"(c));
    return d;
}
__device__ __forceinline__ u64 pack2(float lo, float hi) {
    u64 d;
    asm("mov.b64 %0, {%1, %2};" : "=l"(d) : "f"(lo), "f"(hi));
    return d;
}
__device__ __forceinline__ float sum2(u64 a) {
    float lo, hi;
    asm("mov.b64 {%0, %1}, %2;" : "=f"(lo), "=f"(hi) : "l"(a));
    return lo + hi;
}

// ---------------- device scratch (static allocation is the sanctioned path) ----
__device__ float g_xg[(size_t)BB * TT * G4];   // 512 MB: x@W_ih^T + b_ih + b_hh

// ---------------- xg = x @ W_ih^T + b_ih + b_hh  ->  g_xg[b][t][j] ------------
__global__ void xg_kernel(const float* __restrict__ x,
                          const float* __restrict__ W_ih,
                          const float* __restrict__ b_ih,
                          const float* __restrict__ b_hh) {
    __shared__ __align__(16) float xs[128 * FF];  // 16 KB staging of x[b][t0..t0+128)

    const int b   = blockIdx.y;
    const int tid = threadIdx.x;
    const int w   = tid >> 5, l = tid & 31;
    const int j   = blockIdx.x * 256 + w * 32 + l;

    // W_ih row -> 16 packed f32x2 registers
    u64 wp[FF / 2];
#pragma unroll
    for (int k = 0; k < FF; k += 4) {
        float4 v = *(const float4*)&W_ih[j * FF + k];
        wp[k / 2]     = pack2(v.x, v.y);
        wp[k / 2 + 1] = pack2(v.z, v.w);
    }
    const float bias = b_ih[j] + b_hh[j];

    const float* xb  = x + (size_t)b * TT * FF;
    float*       out = g_xg + (size_t)b * TT * G4 + j;

    for (int t0 = 0; t0 < TT; t0 += 128) {
        __syncthreads();
        {
            const float4* src = (const float4*)(xb + (size_t)t0 * FF);
            float4*       dst = (float4*)xs;
#pragma unroll
            for (int i = tid; i < 128 * FF / 4; i += TPB) dst[i] = src[i];
        }
        __syncthreads();

        for (int tt = 0; tt < 128; tt += 4) {
            u64 a0 = 0, a1 = 0, a2 = 0, a3 = 0;
#pragma unroll
            for (int kq = 0; kq < 8; kq++) {
                ulonglong2 x0 = *(const ulonglong2*)&xs[(tt + 0) * FF + 4 * kq];
                ulonglong2 x1 = *(const ulonglong2*)&xs[(tt + 1) * FF + 4 * kq];
                ulonglong2 x2 = *(const ulonglong2*)&xs[(tt + 2) * FF + 4 * kq];
                ulonglong2 x3 = *(const ulonglong2*)&xs[(tt + 3) * FF + 4 * kq];
                u64 w0 = wp[2 * kq], w1 = wp[2 * kq + 1];
                a0 = fma2(w0, x0.x, a0); a0 = fma2(w1, x0.y, a0);
                a1 = fma2(w0, x1.x, a1); a1 = fma2(w1, x1.y, a1);
                a2 = fma2(w0, x2.x, a2); a2 = fma2(w1, x2.y, a2);
                a3 = fma2(w0, x3.x, a3); a3 = fma2(w1, x3.y, a3);
            }
            out[(size_t)(t0 + tt + 0) * G4] = sum2(a0) + bias;
            out[(size_t)(t0 + tt + 1) * G4] = sum2(a1) + bias;
            out[(size_t)(t0 + tt + 2) * G4] = sum2(a2) + bias;
            out[(size_t)(t0 + tt + 3) * G4] = sum2(a3) + bias;
        }
    }
}

// ---------------- recurrence --------------------------------------------------
__device__ __forceinline__ float sigf(float v) {
    return __fdividef(1.f, 1.f + __expf(-v));
}
__device__ __forceinline__ float tanh_fast(float v) {
    float e = __expf(2.f * v);
    return 1.f - __fdividef(2.f, e + 1.f);
}

// W smem layout: w4s[q][j] = ulonglong2{ pack2(W[j][4q],W[j][4q+1]),
//                                        pack2(W[j][4q+2],W[j][4q+3]) }
// One LDS.128 per row per q (was 2x LDS.64). 32 consecutive j per warp
// -> 512B contiguous per access, conflict-free.

// Both rows from smem.
__device__ __forceinline__ void gemm_smem(const ulonglong2* __restrict__ wa,
                                          const ulonglong2* __restrict__ wb,
                                          const float* __restrict__ hs,
                                          u64 acc0[4], u64 acc1[4]) {
#pragma unroll 8
    for (int q = 0; q < 32; q++) {
        ulonglong2 wA = wa[q * SROWS];
        ulonglong2 wB = wb[q * SROWS];
#pragma unroll
        for (int b = 0; b < 4; b++) {
            ulonglong2 hv = *(const ulonglong2*)(hs + b * HH + 4 * q);
            acc0[b] = fma2(wA.x, hv.x, acc0[b]);
            acc0[b] = fma2(wA.y, hv.y, acc0[b]);
            acc1[b] = fma2(wB.x, hv.x, acc1[b]);
            acc1[b] = fma2(wB.y, hv.y, acc1[b]);
        }
    }
}

// Row A from smem, row B streamed from L2-resident W_hh (row-major, LDG.128).
__device__ __forceinline__ void gemm_mixed(const ulonglong2* __restrict__ wa,
                                           const float* __restrict__ wrow,
                                           const float* __restrict__ hs,
                                           u64 acc0[4], u64 acc1[4]) {
#pragma unroll 8
    for (int q = 0; q < 32; q++) {
        ulonglong2 wA = wa[q * SROWS];
        float4 wb = *(const float4*)(wrow + 4 * q);
        u64 wB0 = pack2(wb.x, wb.y);
        u64 wB1 = pack2(wb.z, wb.w);
#pragma unroll
        for (int b = 0; b < 4; b++) {
            ulonglong2 hv = *(const ulonglong2*)(hs + b * HH + 4 * q);
            acc0[b] = fma2(wA.x, hv.x, acc0[b]);
            acc0[b] = fma2(wA.y, hv.y, acc0[b]);
            acc1[b] = fma2(wB0, hv.x, acc1[b]);
            acc1[b] = fma2(wB1, hv.y, acc1[b]);
        }
    }
}

__global__ __launch_bounds__(TPB, 1)
void lstm_kernel(const float* __restrict__ W_hh,
                 const float* __restrict__ W_fc,
                 const float* __restrict__ b_fc,
                 float* __restrict__ out) {
    extern __shared__ __align__(16) float smem[];
    ulonglong2* w4s = (ulonglong2*)smem;   // [32][SROWS] 16B units  212992 B
    float* gs  = smem + 64 * SROWS * 2;    // gates [4][512]           8192 B
    float* hs  = gs + 4 * G4;              // h     [4][128]           2048 B
    float* cs  = hs + 4 * HH;              // c     [4][128]           2048 B

    const int tid = threadIdx.x;
    const int b0  = blockIdx.x * 4;

    // One-time pack of W_hh rows [0, SROWS) into the smem layout.
    for (int i = tid; i < SROWS * 32; i += TPB) {
        int j = i >> 5;         // gate row
        int q = i & 31;         // 4-k group
        float4 v = *(const float4*)&W_hh[j * HH + 4 * q];
        ulonglong2 e;
        e.x = pack2(v.x, v.y);
        e.y = pack2(v.z, v.w);
        w4s[q * SROWS + j] = e;
    }
    for (int i = tid; i < 4 * HH; i += TPB) { hs[i] = 0.f; cs[i] = 0.f; }
    __syncthreads();

    // Row mapping: j0 = tid in [0,256) -> always smem.
    // j1 = tid + 256: smem while j1 < SROWS (warps 0-4), streamed from W_hh
    // for warps 5-7 (uniform per warp since SROWS = 416 = 256 + 5*32).
    const int  j0 = tid;
    const int  j1 = tid + 256;
    const bool j1Shared = (j1 < SROWS);
    const float* wrow1 = W_hh + (size_t)j1 * HH;

    for (int t = 0; t < TT; t++) {
        // prefetch xg contributions (HBM latency hidden under the GEMM)
        float xv0[4], xv1[4];
#pragma unroll
        for (int b = 0; b < 4; b++) {
            const float* p = g_xg + ((size_t)(b0 + b) * TT + t) * G4;
            xv0[b] = p[j0];
            xv1[b] = p[j1];
        }

        u64 acc0[4] = {0, 0, 0, 0};
        u64 acc1[4] = {0, 0, 0, 0};
        if (j1Shared) {
            gemm_smem(w4s + j0, w4s + j1, hs, acc0, acc1);
        } else {
            gemm_mixed(w4s + j0, wrow1, hs, acc0, acc1);
        }

#pragma unroll
        for (int b = 0; b < 4; b++) {
            gs[b * G4 + j0] = sum2(acc0[b]) + xv0[b];
            gs[b * G4 + j1] = sum2(acc1[b]) + xv1[b];
        }
        __syncthreads();

        // gate nonlinearity + state update: 512 (b,u) pairs over 256 threads
#pragma unroll
        for (int s = 0; s < 2; s++) {
            int p = tid + s * TPB;
            int b = p >> 7, u = p & (HH - 1);
            float gi = gs[b * G4 + u];
            float gf = gs[b * G4 + 128 + u];
            float gg = gs[b * G4 + 256 + u];
            float go = gs[b * G4 + 384 + u];
            float c  = sigf(gf) * cs[b * HH + u] + sigf(gi) * tanh_fast(gg);
            float h  = sigf(go) * tanh_fast(c);
            cs[b * HH + u] = c;
            hs[b * HH + u] = h;
        }
        __syncthreads();
    }

    // FC head on final h: out[b][l] = h . W_fc[l] + b_fc[l]
    if (tid < 4 * LL) {
        int b = tid / LL, li = tid - b * LL;
        float s = b_fc[li];
#pragma unroll 4
        for (int u = 0; u < HH; u++) s += hs[b * HH + u] * W_fc[li * HH + u];
        out[(size_t)(b0 + b) * LL + li] = s;
    }
}

// ---------------- launch ------------------------------------------------------
extern "C" void kernel_launch(void* const* d_in, const int* in_sizes, int n_in,
                              void* d_out, int out_size) {
    const float* x    = (const float*)d_in[0];
    const float* W_ih = (const float*)d_in[1];
    const float* W_hh = (const float*)d_in[2];
    const float* b_ih = (const float*)d_in[3];
    const float* b_hh = (const float*)d_in[4];
    const float* W_fc = (const float*)d_in[5];
    const float* b_fc = (const float*)d_in[6];
    float* out = (float*)d_out;
    (void)in_sizes; (void)n_in; (void)out_size;

    dim3 g(2, BB);
    xg_kernel<<<g, TPB>>>(x, W_ih, b_ih, b_hh);

    const int smem_bytes = (64 * SROWS * 2 + 4 * G4 + 4 * HH + 4 * HH) * (int)sizeof(float); // 225280
    cudaFuncSetAttribute(lstm_kernel, cudaFuncAttributeMaxDynamicSharedMemorySize, smem_bytes);
    lstm_kernel<<<BB / 4, TPB, smem_bytes>>>(W_hh, W_fc, b_fc, out);
}

// round 12
// speedup vs baseline: 1.7355x; 1.7355x over previous
#include <cuda_runtime.h>

#define BB   512
#define TT   512
#define FF   32
#define HH   128
#define G4   512
#define LL   5

#define TPB  256
#define RB   256   // rows 256..511 resident in smem; rows 0..255 in registers

typedef unsigned long long u64;

__device__ __forceinline__ u64 fma2(u64 a, u64 b, u64 c) {
    u64 d;
    asm("fma.rn.f32x2 %0, %1, %2, %3;" : "=l"(d) : "l"(a), "l"(b), "l"(c));
    return d;
}
__device__ __forceinline__ u64 pack2(float lo, float hi) {
    u64 d;
    asm("mov.b64 %0, {%1, %2};" : "=l"(d) : "f"(lo), "f"(hi));
    return d;
}
__device__ __forceinline__ float sum2(u64 a) {
    float lo, hi;
    asm("mov.b64 {%0, %1}, %2;" : "=f"(lo), "=f"(hi) : "l"(a));
    return lo + hi;
}

// ---------------- device scratch ----------------------------------------------
__device__ float      g_xg[(size_t)BB * TT * G4];  // 512 MB: x@W_ih^T + b_ih + b_hh
__device__ ulonglong2 g_W4[32 * G4];               // W_hh k-major: [q][j] = 4 k-values of row j

// ---------------- xg = x @ W_ih^T + b_ih + b_hh (+ pack g_W4 on spare blocks) --
__global__ void xg_kernel(const float* __restrict__ x,
                          const float* __restrict__ W_ih,
                          const float* __restrict__ W_hh,
                          const float* __restrict__ b_ih,
                          const float* __restrict__ b_hh) {
    __shared__ __align__(16) float xs[128 * FF];

    const int b   = blockIdx.y;
    const int tid = threadIdx.x;
    const int w   = tid >> 5, l = tid & 31;
    const int j   = blockIdx.x * 256 + w * 32 + l;

    // side duty: 64 blocks pack W_hh into k-major ulonglong2 layout (1 entry/thread)
    if (blockIdx.x == 0 && b < 64) {
        int gid = b * TPB + tid;            // 0..16383
        int q  = gid >> 9;                  // 0..31
        int jr = gid & (G4 - 1);            // 0..511
        float4 v = *(const float4*)&W_hh[jr * HH + 4 * q];
        ulonglong2 e;
        e.x = pack2(v.x, v.y);
        e.y = pack2(v.z, v.w);
        g_W4[(q << 9) + jr] = e;
    }

    u64 wp[FF / 2];
#pragma unroll
    for (int k = 0; k < FF; k += 4) {
        float4 v = *(const float4*)&W_ih[j * FF + k];
        wp[k / 2]     = pack2(v.x, v.y);
        wp[k / 2 + 1] = pack2(v.z, v.w);
    }
    const float bias = b_ih[j] + b_hh[j];

    const float* xb  = x + (size_t)b * TT * FF;
    float*       out = g_xg + (size_t)b * TT * G4 + j;

    for (int t0 = 0; t0 < TT; t0 += 128) {
        __syncthreads();
        {
            const float4* src = (const float4*)(xb + (size_t)t0 * FF);
            float4*       dst = (float4*)xs;
#pragma unroll
            for (int i = tid; i < 128 * FF / 4; i += TPB) dst[i] = src[i];
        }
        __syncthreads();

        for (int tt = 0; tt < 128; tt += 4) {
            u64 a0 = 0, a1 = 0, a2 = 0, a3 = 0;
#pragma unroll
            for (int kq = 0; kq < 8; kq++) {
                ulonglong2 x0 = *(const ulonglong2*)&xs[(tt + 0) * FF + 4 * kq];
                ulonglong2 x1 = *(const ulonglong2*)&xs[(tt + 1) * FF + 4 * kq];
                ulonglong2 x2 = *(const ulonglong2*)&xs[(tt + 2) * FF + 4 * kq];
                ulonglong2 x3 = *(const ulonglong2*)&xs[(tt + 3) * FF + 4 * kq];
                u64 w0 = wp[2 * kq], w1 = wp[2 * kq + 1];
                a0 = fma2(w0, x0.x, a0); a0 = fma2(w1, x0.y, a0);
                a1 = fma2(w0, x1.x, a1); a1 = fma2(w1, x1.y, a1);
                a2 = fma2(w0, x2.x, a2); a2 = fma2(w1, x2.y, a2);
                a3 = fma2(w0, x3.x, a3); a3 = fma2(w1, x3.y, a3);
            }
            out[(size_t)(t0 + tt + 0) * G4] = sum2(a0) + bias;
            out[(size_t)(t0 + tt + 1) * G4] = sum2(a1) + bias;
            out[(size_t)(t0 + tt + 2) * G4] = sum2(a2) + bias;
            out[(size_t)(t0 + tt + 3) * G4] = sum2(a3) + bias;
        }
    }
}

// ---------------- recurrence --------------------------------------------------
__device__ __forceinline__ float sigf(float v) {
    return __fdividef(1.f, 1.f + __expf(-v));
}
__device__ __forceinline__ float tanh_fast(float v) {
    float e = __expf(2.f * v);
    return 1.f - __fdividef(2.f, e + 1.f);
}

__global__ __launch_bounds__(TPB, 1)
void lstm_kernel(const float* __restrict__ W_fc,
                 const float* __restrict__ b_fc,
                 float* __restrict__ out) {
    extern __shared__ __align__(16) float smem[];
    ulonglong2* ws = (ulonglong2*)smem;     // [32][RB] rows 256..511   131072 B
    float* gs = smem + 32 * RB * 4;         // gates [4][512]             8192 B
    float* hs = gs + 4 * G4;                // h     [4][128]             2048 B
    float* cs = hs + 4 * HH;                // c     [4][128]             2048 B

    const int tid = threadIdx.x;
    const int b0  = blockIdx.x * 4;
    const int j0  = tid;                    // register-resident row
    const int j1  = tid + 256;              // smem-resident row

    // Row A (j0) -> 64 packed u64 held in registers for the whole kernel.
    u64 wp[64];
#pragma unroll
    for (int q = 0; q < 32; q++) {
        ulonglong2 e = g_W4[(q << 9) + j0];
        wp[2 * q]     = e.x;
        wp[2 * q + 1] = e.y;
    }

    // Rows 256..511 -> smem (coalesced load, conflict-free store).
    for (int i = tid; i < 32 * RB; i += TPB) {
        int q  = i >> 8;        // 0..31
        int jj = i & (RB - 1);  // 0..255
        ws[i] = g_W4[(q << 9) + RB + jj];
        (void)jj;
    }
    for (int i = tid; i < 4 * HH; i += TPB) { hs[i] = 0.f; cs[i] = 0.f; }
    __syncthreads();

    for (int t = 0; t < TT; t++) {
        // prefetch xg contributions (DRAM latency hidden under the GEMM)
        float xv0[4], xv1[4];
#pragma unroll
        for (int b = 0; b < 4; b++) {
            const float* p = g_xg + ((size_t)(b0 + b) * TT + t) * G4;
            xv0[b] = p[j0];
            xv1[b] = p[j1];
        }

        u64 acc0[4] = {0, 0, 0, 0};
        u64 acc1[4] = {0, 0, 0, 0};
#pragma unroll
        for (int q = 0; q < 32; q++) {
            ulonglong2 wb = ws[(q << 8) + tid];   // row B, 512B/warp contiguous
#pragma unroll
            for (int b = 0; b < 4; b++) {
                ulonglong2 hv = *(const ulonglong2*)(hs + b * HH + 4 * q);
                acc0[b] = fma2(wp[2 * q],     hv.x, acc0[b]);
                acc0[b] = fma2(wp[2 * q + 1], hv.y, acc0[b]);
                acc1[b] = fma2(wb.x,          hv.x, acc1[b]);
                acc1[b] = fma2(wb.y,          hv.y, acc1[b]);
            }
        }

#pragma unroll
        for (int b = 0; b < 4; b++) {
            gs[b * G4 + j0] = sum2(acc0[b]) + xv0[b];
            gs[b * G4 + j1] = sum2(acc1[b]) + xv1[b];
        }
        __syncthreads();

        // gate nonlinearity + state update
#pragma unroll
        for (int s = 0; s < 2; s++) {
            int p = tid + s * TPB;
            int b = p >> 7, u = p & (HH - 1);
            float gi = gs[b * G4 + u];
            float gf = gs[b * G4 + 128 + u];
            float gg = gs[b * G4 + 256 + u];
            float go = gs[b * G4 + 384 + u];
            float c  = sigf(gf) * cs[b * HH + u] + sigf(gi) * tanh_fast(gg);
            float h  = sigf(go) * tanh_fast(c);
            cs[b * HH + u] = c;
            hs[b * HH + u] = h;
        }
        __syncthreads();
    }

    // FC head
    if (tid < 4 * LL) {
        int b = tid / LL, li = tid - b * LL;
        float s = b_fc[li];
#pragma unroll 4
        for (int u = 0; u < HH; u++) s += hs[b * HH + u] * W_fc[li * HH + u];
        out[(size_t)(b0 + b) * LL + li] = s;
    }
}

// ---------------- launch ------------------------------------------------------
extern "C" void kernel_launch(void* const* d_in, const int* in_sizes, int n_in,
                              void* d_out, int out_size) {
    const float* x    = (const float*)d_in[0];
    const float* W_ih = (const float*)d_in[1];
    const float* W_hh = (const float*)d_in[2];
    const float* b_ih = (const float*)d_in[3];
    const float* b_hh = (const float*)d_in[4];
    const float* W_fc = (const float*)d_in[5];
    const float* b_fc = (const float*)d_in[6];
    float* out = (float*)d_out;
    (void)in_sizes; (void)n_in; (void)out_size;

    dim3 g(2, BB);
    xg_kernel<<<g, TPB>>>(x, W_ih, W_hh, b_ih, b_hh);

    const int smem_bytes = (32 * RB * 4 + 4 * G4 + 4 * HH + 4 * HH) * (int)sizeof(float); // 143360
    cudaFuncSetAttribute(lstm_kernel, cudaFuncAttributeMaxDynamicSharedMemorySize, smem_bytes);
    lstm_kernel<<<BB / 4, TPB, smem_bytes>>>(W_fc, b_fc, out);
}

// round 16
// speedup vs baseline: 1.7834x; 1.0276x over previous
#include <cuda_runtime.h>

#define BB   512
#define TT   512
#define FF   32
#define HH   128
#define G4   512
#define LL   5

#define TPB  256
#define SMR  128   // rows 256..383 in smem; 0..255 in regs; 384..511 L2-streamed

typedef unsigned long long u64;

__device__ __forceinline__ u64 fma2(u64 a, u64 b, u64 c) {
    u64 d;
    asm("fma.rn.f32x2 %0, %1, %2, %3;" : "=l"(d) : "l"(a), "l"(b), "l"(c));
    return d;
}
__device__ __forceinline__ u64 pack2(float lo, float hi) {
    u64 d;
    asm("mov.b64 %0, {%1, %2};" : "=l"(d) : "f"(lo), "f"(hi));
    return d;
}
__device__ __forceinline__ float sum2(u64 a) {
    float lo, hi;
    asm("mov.b64 {%0, %1}, %2;" : "=f"(lo), "=f"(hi) : "l"(a));
    return lo + hi;
}

// ---------------- device scratch ----------------------------------------------
__device__ float      g_xg[(size_t)BB * TT * G4];  // 512 MB
__device__ ulonglong2 g_W4[32 * G4];               // W_hh k-major: [q][j]

// ---------------- xg kernel (+ pack g_W4 on spare blocks) ----------------------
__global__ void xg_kernel(const float* __restrict__ x,
                          const float* __restrict__ W_ih,
                          const float* __restrict__ W_hh,
                          const float* __restrict__ b_ih,
                          const float* __restrict__ b_hh) {
    __shared__ __align__(16) float xs[128 * FF];

    const int b   = blockIdx.y;
    const int tid = threadIdx.x;
    const int w   = tid >> 5, l = tid & 31;
    const int j   = blockIdx.x * 256 + w * 32 + l;

    if (blockIdx.x == 0 && b < 64) {
        int gid = b * TPB + tid;
        int q  = gid >> 9;
        int jr = gid & (G4 - 1);
        float4 v = *(const float4*)&W_hh[jr * HH + 4 * q];
        ulonglong2 e;
        e.x = pack2(v.x, v.y);
        e.y = pack2(v.z, v.w);
        g_W4[(q << 9) + jr] = e;
    }

    u64 wp[FF / 2];
#pragma unroll
    for (int k = 0; k < FF; k += 4) {
        float4 v = *(const float4*)&W_ih[j * FF + k];
        wp[k / 2]     = pack2(v.x, v.y);
        wp[k / 2 + 1] = pack2(v.z, v.w);
    }
    const float bias = b_ih[j] + b_hh[j];

    const float* xb  = x + (size_t)b * TT * FF;
    float*       out = g_xg + (size_t)b * TT * G4 + j;

    for (int t0 = 0; t0 < TT; t0 += 128) {
        __syncthreads();
        {
            const float4* src = (const float4*)(xb + (size_t)t0 * FF);
            float4*       dst = (float4*)xs;
#pragma unroll
            for (int i = tid; i < 128 * FF / 4; i += TPB) dst[i] = src[i];
        }
        __syncthreads();

        for (int tt = 0; tt < 128; tt += 4) {
            u64 a0 = 0, a1 = 0, a2 = 0, a3 = 0;
#pragma unroll
            for (int kq = 0; kq < 8; kq++) {
                ulonglong2 x0 = *(const ulonglong2*)&xs[(tt + 0) * FF + 4 * kq];
                ulonglong2 x1 = *(const ulonglong2*)&xs[(tt + 1) * FF + 4 * kq];
                ulonglong2 x2 = *(const ulonglong2*)&xs[(tt + 2) * FF + 4 * kq];
                ulonglong2 x3 = *(const ulonglong2*)&xs[(tt + 3) * FF + 4 * kq];
                u64 w0 = wp[2 * kq], w1 = wp[2 * kq + 1];
                a0 = fma2(w0, x0.x, a0); a0 = fma2(w1, x0.y, a0);
                a1 = fma2(w0, x1.x, a1); a1 = fma2(w1, x1.y, a1);
                a2 = fma2(w0, x2.x, a2); a2 = fma2(w1, x2.y, a2);
                a3 = fma2(w0, x3.x, a3); a3 = fma2(w1, x3.y, a3);
            }
            out[(size_t)(t0 + tt + 0) * G4] = sum2(a0) + bias;
            out[(size_t)(t0 + tt + 1) * G4] = sum2(a1) + bias;
            out[(size_t)(t0 + tt + 2) * G4] = sum2(a2) + bias;
            out[(size_t)(t0 + tt + 3) * G4] = sum2(a3) + bias;
        }
    }
}

// ---------------- recurrence --------------------------------------------------
__device__ __forceinline__ float sigf(float v) {
    return __fdividef(1.f, 1.f + __expf(-v));
}
__device__ __forceinline__ float tanh_fast(float v) {
    float e = __expf(2.f * v);
    return 1.f - __fdividef(2.f, e + 1.f);
}

// Row A in registers; row B from smem (stride 128) or L2 (stride 512).
template <int SB>
__device__ __forceinline__ void gemm_row(const u64* __restrict__ wp,
                                         const ulonglong2* __restrict__ wbp,
                                         const float* __restrict__ hs,
                                         u64 acc0[4], u64 acc1[4]) {
#pragma unroll
    for (int q = 0; q < 32; q++) {
        ulonglong2 wb = wbp[q * SB];
#pragma unroll
        for (int b = 0; b < 4; b++) {
            ulonglong2 hv = *(const ulonglong2*)(hs + b * HH + 4 * q);
            acc0[b] = fma2(wp[2 * q],     hv.x, acc0[b]);
            acc0[b] = fma2(wp[2 * q + 1], hv.y, acc0[b]);
            acc1[b] = fma2(wb.x,          hv.x, acc1[b]);
            acc1[b] = fma2(wb.y,          hv.y, acc1[b]);
        }
    }
}

__global__ __launch_bounds__(TPB, 1)
void lstm_kernel(const float* __restrict__ W_fc,
                 const float* __restrict__ b_fc,
                 float* __restrict__ out) {
    extern __shared__ __align__(16) float smem[];
    ulonglong2* ws = (ulonglong2*)smem;     // [32][SMR] rows 256..383   65536 B
    float* gs = smem + 32 * SMR * 4;        // gates [4][512]             8192 B
    float* hs = gs + 4 * G4;                // h     [4][128]             2048 B
    float* cs = hs + 4 * HH;                // c     [4][128]             2048 B

    const int tid = threadIdx.x;
    const int b0  = blockIdx.x * 4;
    const int j0  = tid;                    // register-resident row
    const int j1  = tid + 256;              // smem row (tid<128) or L2 row

    // Row A (j0) -> 64 packed u64 in registers for the whole kernel.
    u64 wp[64];
#pragma unroll
    for (int q = 0; q < 32; q++) {
        ulonglong2 e = g_W4[(q << 9) + j0];
        wp[2 * q]     = e.x;
        wp[2 * q + 1] = e.y;
    }

    // Rows 256..383 -> smem (coalesced load, conflict-free store).
    for (int i = tid; i < 32 * SMR; i += TPB) {
        int q  = i >> 7;
        int jj = i & (SMR - 1);
        ws[i] = g_W4[(q << 9) + 256 + jj];
    }
    for (int i = tid; i < 4 * HH; i += TPB) { hs[i] = 0.f; cs[i] = 0.f; }
    __syncthreads();

    const bool j1Shared = (tid < SMR);

    for (int t = 0; t < TT; t++) {
        float xv0[4], xv1[4];
#pragma unroll
        for (int b = 0; b < 4; b++) {
            const float* p = g_xg + ((size_t)(b0 + b) * TT + t) * G4;
            xv0[b] = p[j0];
            xv1[b] = p[j1];
        }

        u64 acc0[4] = {0, 0, 0, 0};
        u64 acc1[4] = {0, 0, 0, 0};
        if (j1Shared) {
            gemm_row<SMR>(wp, ws + tid, hs, acc0, acc1);
        } else {
            gemm_row<G4>(wp, g_W4 + j1, hs, acc0, acc1);
        }

#pragma unroll
        for (int b = 0; b < 4; b++) {
            gs[b * G4 + j0] = sum2(acc0[b]) + xv0[b];
            gs[b * G4 + j1] = sum2(acc1[b]) + xv1[b];
        }
        __syncthreads();

#pragma unroll
        for (int s = 0; s < 2; s++) {
            int p = tid + s * TPB;
            int b = p >> 7, u = p & (HH - 1);
            float gi = gs[b * G4 + u];
            float gf = gs[b * G4 + 128 + u];
            float gg = gs[b * G4 + 256 + u];
            float go = gs[b * G4 + 384 + u];
            float c  = sigf(gf) * cs[b * HH + u] + sigf(gi) * tanh_fast(gg);
            float h  = sigf(go) * tanh_fast(c);
            cs[b * HH + u] = c;
            hs[b * HH + u] = h;
        }
        __syncthreads();
    }

    if (tid < 4 * LL) {
        int b = tid / LL, li = tid - b * LL;
        float s = b_fc[li];
#pragma unroll 4
        for (int u = 0; u < HH; u++) s += hs[b * HH + u] * W_fc[li * HH + u];
        out[(size_t)(b0 + b) * LL + li] = s;
    }
}

// ---------------- launch ------------------------------------------------------
extern "C" void kernel_launch(void* const* d_in, const int* in_sizes, int n_in,
                              void* d_out, int out_size) {
    const float* x    = (const float*)d_in[0];
    const float* W_ih = (const float*)d_in[1];
    const float* W_hh = (const float*)d_in[2];
    const float* b_ih = (const float*)d_in[3];
    const float* b_hh = (const float*)d_in[4];
    const float* W_fc = (const float*)d_in[5];
    const float* b_fc = (const float*)d_in[6];
    float* out = (float*)d_out;
    (void)in_sizes; (void)n_in; (void)out_size;

    dim3 g(2, BB);
    xg_kernel<<<g, TPB>>>(x, W_ih, W_hh, b_ih, b_hh);

    const int smem_bytes = (32 * SMR * 4 + 4 * G4 + 4 * HH + 4 * HH) * (int)sizeof(float); // 77824
    cudaFuncSetAttribute(lstm_kernel, cudaFuncAttributeMaxDynamicSharedMemorySize, smem_bytes);
    lstm_kernel<<<BB / 4, TPB, smem_bytes>>>(W_fc, b_fc, out);
}